// round 14
// baseline (speedup 1.0000x reference)
#include <cuda_runtime.h>

#define B_   4
#define S_   2048
#define H_   16
#define HID_ 2048
#define DK_  128
#define DV_  128
#define P_   (B_*S_)   // 8192 positions

// scratch (allowed: __device__ globals)
__device__ float g_decay[P_*H_];
__device__ float g_beta [P_*H_];

// ============================================================
// Kernel 1: gating GEMM  raw = x @ [Wa;Wb]^T  + epilogue
// ============================================================
#define GT_POS 64
#define GT_K   32

__global__ __launch_bounds__(256) void gate_kernel(
    const float* __restrict__ x,
    const float* __restrict__ Wa, const float* __restrict__ Wb,
    const float* __restrict__ dt_bias, const float* __restrict__ A_log)
{
    __shared__ float xs[GT_POS][GT_K+1];
    __shared__ float ws[32][GT_K+1];
    int t  = threadIdx.x;
    int p0 = blockIdx.x * GT_POS;
    int tx = t & 7;
    int ty = t >> 3;
    float acc[2][4] = {};

    for (int kc = 0; kc < HID_; kc += GT_K) {
        #pragma unroll
        for (int i = 0; i < (GT_POS*GT_K)/256; ++i) {
            int e = i*256 + t; int r = e >> 5, c = e & 31;
            xs[r][c] = x[(size_t)(p0 + r)*HID_ + kc + c];
        }
        #pragma unroll
        for (int i = 0; i < (32*GT_K)/256; ++i) {
            int e = i*256 + t; int f = e >> 5, c = e & 31;
            const float* wrow = (f < 16) ? (Wa + f*HID_) : (Wb + (f-16)*HID_);
            ws[f][c] = wrow[kc + c];
        }
        __syncthreads();
        #pragma unroll
        for (int k = 0; k < GT_K; ++k) {
            float xv0 = xs[2*ty  ][k];
            float xv1 = xs[2*ty+1][k];
            #pragma unroll
            for (int j = 0; j < 4; ++j) {
                float wv = ws[4*tx+j][k];
                acc[0][j] = fmaf(xv0, wv, acc[0][j]);
                acc[1][j] = fmaf(xv1, wv, acc[1][j]);
            }
        }
        __syncthreads();
    }

    #pragma unroll
    for (int i = 0; i < 2; ++i) {
        int p = p0 + 2*ty + i;
        #pragma unroll
        for (int j = 0; j < 4; ++j) {
            int f = 4*tx + j;
            float r = acc[i][j];
            if (f < 16) {
                float z  = r + __ldg(dt_bias + f);
                float sp = fmaxf(z, 0.0f) + log1pf(expf(-fabsf(z)));
                g_decay[p*H_ + f] = expf(-expf(__ldg(A_log + f)) * sp);
            } else {
                g_beta[p*H_ + (f-16)] = r;
            }
        }
    }
}

// ============================================================
// Kernel 2: delta-rule scan, 2 cols per lane (C=2) + smem
// broadcast staging. CTA = 128 thr = 4 warps x 8 cols; grid =
// 64 bh x 4 colcta = 256 CTAs.
// Lane (cp = lane>>3 owns col pair, sub = lane&7) owns the 4
// chunks {sub + 8t}, t=0..3 (chunk = 4 rows; 16 rows total) for
// its 2 cols -> 16 u64 state st[(t*2+rp)*2 + c].
// SMEM ring: 8 slots x {k,q} x 32 float4. Swizzle:
//   fill: chunk c -> index (c&7) + 8*(((c>>3)+(c&7))&3)
//   read: t-th LDS at  sub + 8*((t+sub)&3)
// idx mod 8 = sub => 8 distinct rows per LDS, 4-way cp-broadcast,
// conflict-free both directions; fill STS is a bijection.
// Per step:
//   p[c]  = redux8( k . S[:,col_c] )   (hadd + xor1,2,4)
//   d[c]  = (v[c] - g*p[c]) * beta
//   S     = g*S + k (x) d
//   o[c]  = redux8( q . S_new[:,col_c] )  (off recurrence path)
// ============================================================
typedef unsigned long long u64;

__device__ __forceinline__ u64 fma2(u64 a, u64 b, u64 c) {
    u64 d; asm("fma.rn.f32x2 %0, %1, %2, %3;" : "=l"(d) : "l"(a), "l"(b), "l"(c));
    return d;
}
__device__ __forceinline__ u64 mul2(u64 a, u64 b) {
    u64 d; asm("mul.rn.f32x2 %0, %1, %2;" : "=l"(d) : "l"(a), "l"(b));
    return d;
}
__device__ __forceinline__ u64 pack2(float x, float y) {
    u64 d; asm("mov.b64 %0, {%1, %2};" : "=l"(d)
               : "r"(__float_as_uint(x)), "r"(__float_as_uint(y)));
    return d;
}
__device__ __forceinline__ float hadd2(u64 a) {
    unsigned lo, hi;
    asm("mov.b64 {%0, %1}, %2;" : "=r"(lo), "=r"(hi) : "l"(a));
    return __uint_as_float(lo) + __uint_as_float(hi);
}

struct QuadPre {                 // prefetched v/g/beta for 4 steps
    float2 v[4];
    float g[4], b[4];
};

__device__ __forceinline__ void load_quad(QuadPre& p,
    const float* vb, const float* gb, const float* bb, int s, int vq)
{
    #pragma unroll
    for (int i = 0; i < 4; ++i) {
        int si = s + i; if (si > S_ - 1) si = S_ - 1;
        p.v[i] = __ldg((const float2*)(vb + (size_t)si * (H_*DK_)) + vq);
        p.g[i] = __ldg(gb + (size_t)si * H_);
        p.b[i] = __ldg(bb + (size_t)si * H_);
    }
}

// one scan step; slotbase in float4 units (slot*64)
__device__ __forceinline__ void do_step(const float4* sm, int slotbase,
                                        const int ofs[4], u64 st[16],
                                        float2 vv, float g, float be,
                                        float* outp, int sub, int vq)
{
    const unsigned FM = 0xffffffffu;
    const float4* kreg = sm + slotbase;
    const float4* qreg = sm + slotbase + 32;

    u64 k2[8];
    #pragma unroll
    for (int t = 0; t < 4; ++t) {
        ulonglong2 kk = *reinterpret_cast<const ulonglong2*>(kreg + ofs[t]);
        k2[2*t] = kk.x; k2[2*t+1] = kk.y;
    }

    // ---- p[c] = k . S[:,col_c] ----
    u64 pa0 = mul2(k2[0], st[0]);
    u64 pa1 = mul2(k2[0], st[1]);
    u64 pb0 = mul2(k2[1], st[2]);
    u64 pb1 = mul2(k2[1], st[3]);
    #pragma unroll
    for (int i = 2; i < 8; i += 2) {
        pa0 = fma2(k2[i],   st[(i  )*2+0], pa0);
        pa1 = fma2(k2[i],   st[(i  )*2+1], pa1);
        pb0 = fma2(k2[i+1], st[(i+1)*2+0], pb0);
        pb1 = fma2(k2[i+1], st[(i+1)*2+1], pb1);
    }
    float p0 = hadd2(pa0) + hadd2(pb0);
    float p1 = hadd2(pa1) + hadd2(pb1);
    p0 += __shfl_xor_sync(FM, p0, 1);
    p1 += __shfl_xor_sync(FM, p1, 1);
    p0 += __shfl_xor_sync(FM, p0, 2);
    p1 += __shfl_xor_sync(FM, p1, 2);
    p0 += __shfl_xor_sync(FM, p0, 4);
    p1 += __shfl_xor_sync(FM, p1, 4);

    // ---- delta ----
    float d0 = fmaf(-g, p0, vv.x) * be;
    float d1 = fmaf(-g, p1, vv.y) * be;

    // ---- state update: S = g*S + k (x) d ----
    u64 gp  = pack2(g, g);
    u64 d02 = pack2(d0, d0);
    u64 d12 = pack2(d1, d1);
    #pragma unroll
    for (int i = 0; i < 8; ++i) {
        st[i*2+0] = fma2(k2[i], d02, mul2(gp, st[i*2+0]));
        st[i*2+1] = fma2(k2[i], d12, mul2(gp, st[i*2+1]));
    }

    // ---- o[c] = q . S_new[:,col_c] (off recurrence path) ----
    u64 q2[8];
    #pragma unroll
    for (int t = 0; t < 4; ++t) {
        ulonglong2 qq = *reinterpret_cast<const ulonglong2*>(qreg + ofs[t]);
        q2[2*t] = qq.x; q2[2*t+1] = qq.y;
    }
    u64 oa0 = mul2(q2[0], st[0]);
    u64 oa1 = mul2(q2[0], st[1]);
    u64 ob0 = mul2(q2[1], st[2]);
    u64 ob1 = mul2(q2[1], st[3]);
    #pragma unroll
    for (int i = 2; i < 8; i += 2) {
        oa0 = fma2(q2[i],   st[(i  )*2+0], oa0);
        oa1 = fma2(q2[i],   st[(i  )*2+1], oa1);
        ob0 = fma2(q2[i+1], st[(i+1)*2+0], ob0);
        ob1 = fma2(q2[i+1], st[(i+1)*2+1], ob1);
    }
    float o0 = hadd2(oa0) + hadd2(ob0);
    float o1 = hadd2(oa1) + hadd2(ob1);
    o0 += __shfl_xor_sync(FM, o0, 1);
    o1 += __shfl_xor_sync(FM, o1, 1);
    o0 += __shfl_xor_sync(FM, o0, 2);
    o1 += __shfl_xor_sync(FM, o1, 2);
    o0 += __shfl_xor_sync(FM, o0, 4);
    o1 += __shfl_xor_sync(FM, o1, 4);

    if (sub == 0)
        ((float2*)outp)[vq] = make_float2(o0, o1);
}

__global__ void __launch_bounds__(128, 3) scan_kernel(
    const float* __restrict__ q, const float* __restrict__ k,
    const float* __restrict__ v, float* __restrict__ out)
{
    // smem ring: 8 slots x {k,q} x 32 float4 (8 KB)
    __shared__ float4 sm[8*2*32];

    int bid    = blockIdx.x;         // 256 CTAs
    int colcta = bid & 3;            // 32-col slice
    int bh     = bid >> 2;
    int b      = bh >> 4, h = bh & 15;
    int tid    = threadIdx.x;
    int w      = tid >> 5;           // warp 0..3
    int lane   = tid & 31;
    int cp     = lane >> 3;          // col-pair owner 0..3
    int sub    = lane & 7;           // row slice 0..7
    int col0   = colcta*32 + w*8 + cp*2;
    int vq     = col0 >> 1;          // float2 index

    size_t base = ((size_t)b * S_ * H_ + h) * DK_;
    const float* kb = k + base;
    const float* qb = q + base;
    const float* vb = v + base;
    float*       ob = out + base;
    const float* gb = g_decay + (size_t)b * S_ * H_ + h;
    const float* bb = g_beta  + (size_t)b * S_ * H_ + h;

    // consumer LDS offsets (float4 units within a 32-float4 region)
    int ofs[4];
    #pragma unroll
    for (int t = 0; t < 4; ++t)
        ofs[t] = sub + 8*((t + sub) & 3);

    // fill params: warp w stages vector (w&1) of slot-parity (w>>1)
    int fvec  = w & 1;               // 0 = k, 1 = q
    int fsoff = w >> 1;              // 0 or 1
    int fidx  = (lane & 7) + 8*((((lane >> 3) + (lane & 7))) & 3);
    const float* fsrc = fvec ? qb : kb;

    // ---- pre-fill slots 0..7 = steps 0..7 (each warp: 4 slots) ----
    #pragma unroll
    for (int i = 0; i < 4; ++i) {
        int fs = fsoff + 2*i;        // slots {0,2,4,6} or {1,3,5,7}
        float4 val = __ldg((const float4*)(fsrc + (size_t)fs*(H_*DK_)) + lane);
        sm[(fs*2 + fvec)*32 + fidx] = val;
    }
    __syncthreads();

    u64 st[16];
    #pragma unroll
    for (int j = 0; j < 16; ++j) st[j] = 0ull;

    QuadPre P0, P1;
    load_quad(P0, vb, gb, bb, 0, vq);

    for (int s = 0; s < S_; s += 8) {
        load_quad(P1, vb, gb, bb, s + 4, vq);

        // ---- consume slots 0..3 (steps s..s+3) ----
        do_step(sm, 0*64, ofs, st, P0.v[0], P0.g[0], P0.b[0], ob + (size_t)(s  )*(H_*DV_), sub, vq);
        do_step(sm, 1*64, ofs, st, P0.v[1], P0.g[1], P0.b[1], ob + (size_t)(s+1)*(H_*DV_), sub, vq);
        do_step(sm, 2*64, ofs, st, P0.v[2], P0.g[2], P0.b[2], ob + (size_t)(s+2)*(H_*DV_), sub, vq);
        do_step(sm, 3*64, ofs, st, P0.v[3], P0.g[3], P0.b[3], ob + (size_t)(s+3)*(H_*DV_), sub, vq);

        __syncthreads();   // slots 0..3 consumed by all warps

        // fill slots 0..3 <- steps s+8..s+11 (warp w: slots fsoff, fsoff+2)
        {
            int s0 = s + 8 + fsoff;   if (s0 > S_ - 1) s0 = S_ - 1;
            int s1 = s + 10 + fsoff;  if (s1 > S_ - 1) s1 = S_ - 1;
            float4 v0 = __ldg((const float4*)(fsrc + (size_t)s0*(H_*DK_)) + lane);
            float4 v1 = __ldg((const float4*)(fsrc + (size_t)s1*(H_*DK_)) + lane);
            sm[((fsoff    )*2 + fvec)*32 + fidx] = v0;
            sm[((fsoff + 2)*2 + fvec)*32 + fidx] = v1;
        }
        load_quad(P0, vb, gb, bb, s + 8, vq);   // for next iteration

        // ---- consume slots 4..7 (steps s+4..s+7) ----
        do_step(sm, 4*64, ofs, st, P1.v[0], P1.g[0], P1.b[0], ob + (size_t)(s+4)*(H_*DV_), sub, vq);
        do_step(sm, 5*64, ofs, st, P1.v[1], P1.g[1], P1.b[1], ob + (size_t)(s+5)*(H_*DV_), sub, vq);
        do_step(sm, 6*64, ofs, st, P1.v[2], P1.g[2], P1.b[2], ob + (size_t)(s+6)*(H_*DV_), sub, vq);
        do_step(sm, 7*64, ofs, st, P1.v[3], P1.g[3], P1.b[3], ob + (size_t)(s+7)*(H_*DV_), sub, vq);

        __syncthreads();   // slots 4..7 consumed

        // fill slots 4..7 <- steps s+12..s+15 (RAW ordered by next iter's
        // first barrier)
        {
            int s2 = s + 12 + fsoff;  if (s2 > S_ - 1) s2 = S_ - 1;
            int s3 = s + 14 + fsoff;  if (s3 > S_ - 1) s3 = S_ - 1;
            float4 v2 = __ldg((const float4*)(fsrc + (size_t)s2*(H_*DK_)) + lane);
            float4 v3 = __ldg((const float4*)(fsrc + (size_t)s3*(H_*DK_)) + lane);
            sm[((4 + fsoff)*2 + fvec)*32 + fidx] = v2;
            sm[((6 + fsoff)*2 + fvec)*32 + fidx] = v3;
        }
    }
}

// ============================================================
extern "C" void kernel_launch(void* const* d_in, const int* in_sizes, int n_in,
                              void* d_out, int out_size)
{
    (void)in_sizes; (void)n_in; (void)out_size;
    const float* x   = (const float*)d_in[0];
    const float* q   = (const float*)d_in[1];
    const float* k   = (const float*)d_in[2];
    const float* v   = (const float*)d_in[3];
    const float* Wa  = (const float*)d_in[4];
    const float* Wb  = (const float*)d_in[5];
    const float* dtb = (const float*)d_in[6];
    const float* Al  = (const float*)d_in[7];
    float* out = (float*)d_out;

    gate_kernel<<<P_/GT_POS, 256>>>(x, Wa, Wb, dtb, Al);
    scan_kernel<<<B_*H_*4, 128>>>(q, k, v, out);
}

// round 15
// speedup vs baseline: 1.0496x; 1.0496x over previous
#include <cuda_runtime.h>

#define B_   4
#define S_   2048
#define H_   16
#define HID_ 2048
#define DK_  128
#define DV_  128
#define P_   (B_*S_)   // 8192 positions
#define NC_  256       // chunks per (b,h)
#define CT_  8         // chunk length

// scratch (allowed: __device__ globals)
__device__ float g_decay[P_*H_];
__device__ float g_beta [P_*H_];
// per-(bh,chunk) coefficient block, 160 floats:
// [0..7]=b_i  [8..15]=beta_i  [16..23]=G_i  [24..31]=F_j
// [32..95]=M[i][j] (row-major 8x8, j<i valid)
// [96..159]=N[i][j] (row-major 8x8, j<=i valid)
__device__ float g_coef[B_*H_*NC_*160];

// ============================================================
// Kernel 1: gating GEMM  raw = x @ [Wa;Wb]^T  + epilogue
// ============================================================
#define GT_POS 64
#define GT_K   32

__global__ __launch_bounds__(256) void gate_kernel(
    const float* __restrict__ x,
    const float* __restrict__ Wa, const float* __restrict__ Wb,
    const float* __restrict__ dt_bias, const float* __restrict__ A_log)
{
    __shared__ float xs[GT_POS][GT_K+1];
    __shared__ float ws[32][GT_K+1];
    int t  = threadIdx.x;
    int p0 = blockIdx.x * GT_POS;
    int tx = t & 7;
    int ty = t >> 3;
    float acc[2][4] = {};

    for (int kc = 0; kc < HID_; kc += GT_K) {
        #pragma unroll
        for (int i = 0; i < (GT_POS*GT_K)/256; ++i) {
            int e = i*256 + t; int r = e >> 5, c = e & 31;
            xs[r][c] = x[(size_t)(p0 + r)*HID_ + kc + c];
        }
        #pragma unroll
        for (int i = 0; i < (32*GT_K)/256; ++i) {
            int e = i*256 + t; int f = e >> 5, c = e & 31;
            const float* wrow = (f < 16) ? (Wa + f*HID_) : (Wb + (f-16)*HID_);
            ws[f][c] = wrow[kc + c];
        }
        __syncthreads();
        #pragma unroll
        for (int kk = 0; kk < GT_K; ++kk) {
            float xv0 = xs[2*ty  ][kk];
            float xv1 = xs[2*ty+1][kk];
            #pragma unroll
            for (int j = 0; j < 4; ++j) {
                float wv = ws[4*tx+j][kk];
                acc[0][j] = fmaf(xv0, wv, acc[0][j]);
                acc[1][j] = fmaf(xv1, wv, acc[1][j]);
            }
        }
        __syncthreads();
    }

    #pragma unroll
    for (int i = 0; i < 2; ++i) {
        int p = p0 + 2*ty + i;
        #pragma unroll
        for (int j = 0; j < 4; ++j) {
            int f = 4*tx + j;
            float r = acc[i][j];
            if (f < 16) {
                float z  = r + __ldg(dt_bias + f);
                float sp = fmaxf(z, 0.0f) + log1pf(expf(-fabsf(z)));
                g_decay[p*H_ + f] = expf(-expf(__ldg(A_log + f)) * sp);
            } else {
                g_beta[p*H_ + (f-16)] = r;
            }
        }
    }
}

// ============================================================
// Kernel 1.5: per-chunk coefficient precompute (warp per chunk).
// Computes pair dots K_ij = k_i.k_j, QK_ij = q_i.k_j over DK,
// then the UT-transform coefficient block (see g_coef layout).
// All within-chunk decay products computed as PRODUCTS (no
// ratios) so underflow-to-0 matches sequential semantics.
// ============================================================
__global__ __launch_bounds__(128) void coef_kernel(
    const float* __restrict__ q, const float* __restrict__ k)
{
    __shared__ float KS[4][64];
    __shared__ float QS[4][64];
    __shared__ float CO[4][160];
    int w    = threadIdx.x >> 5;
    int lane = threadIdx.x & 31;
    int gw   = blockIdx.x * 4 + w;       // 0..16383
    int bh   = gw >> 8;
    int ch   = gw & 255;
    int b    = bh >> 4, h = bh & 15;
    int t0   = ch * CT_;

    size_t base = ((size_t)b * S_ * H_ + h) * DK_;
    const float* kb = k + base;
    const float* qb = q + base;
    const float* gb = g_decay + (size_t)b*S_*H_ + h;
    const float* bb = g_beta  + (size_t)b*S_*H_ + h;

    float4 kx[8], qx[8];
    #pragma unroll
    for (int i = 0; i < 8; ++i) {
        kx[i] = __ldg((const float4*)(kb + (size_t)(t0+i)*(H_*DK_)) + lane);
        qx[i] = __ldg((const float4*)(qb + (size_t)(t0+i)*(H_*DK_)) + lane);
    }

    #pragma unroll
    for (int i = 0; i < 8; ++i) {
        #pragma unroll
        for (int j = 0; j <= i; ++j) {
            if (j < i) {
                float s = kx[i].x*kx[j].x + kx[i].y*kx[j].y
                        + kx[i].z*kx[j].z + kx[i].w*kx[j].w;
                #pragma unroll
                for (int m = 1; m < 32; m <<= 1)
                    s += __shfl_xor_sync(0xffffffffu, s, m);
                if (lane == 0) KS[w][i*8+j] = s;
            }
            float t = qx[i].x*kx[j].x + qx[i].y*kx[j].y
                    + qx[i].z*kx[j].z + qx[i].w*kx[j].w;
            #pragma unroll
            for (int m = 1; m < 32; m <<= 1)
                t += __shfl_xor_sync(0xffffffffu, t, m);
            if (lane == 0) QS[w][i*8+j] = t;
        }
    }
    __syncwarp();

    if (lane == 0) {
        float g[8], be[8];
        #pragma unroll
        for (int i = 0; i < 8; ++i) {
            g[i]  = __ldg(gb + (size_t)(t0+i)*H_);
            be[i] = __ldg(bb + (size_t)(t0+i)*H_);
        }
        float G[8];
        G[0] = g[0];
        #pragma unroll
        for (int m = 1; m < 8; ++m) G[m] = G[m-1]*g[m];
        float F[8];
        F[7] = 1.0f;
        #pragma unroll
        for (int j = 6; j >= 0; --j) F[j] = F[j+1]*g[j+1];
        #pragma unroll
        for (int i = 0; i < 8; ++i) {
            CO[w][i]      = be[i]*g[i]*(i ? G[i-1] : 1.0f);  // b_i
            CO[w][8+i]    = be[i];
            CO[w][16+i]   = G[i];
            CO[w][24+i]   = F[i];
        }
        #pragma unroll
        for (int i = 0; i < 8; ++i) {
            float D = 1.0f;
            #pragma unroll
            for (int j = 7; j >= 0; --j) {
                if (j < i) {
                    CO[w][32+i*8+j] = be[i]*g[i]*D*KS[w][i*8+j];
                    D *= g[j];
                } else {
                    CO[w][32+i*8+j] = 0.0f;
                }
            }
            float E = 1.0f;
            #pragma unroll
            for (int j = 7; j >= 0; --j) {
                if (j <= i) {
                    CO[w][96+i*8+j] = E*QS[w][i*8+j];
                    E *= g[j];
                } else {
                    CO[w][96+i*8+j] = 0.0f;
                }
            }
        }
    }
    __syncwarp();
    float* dst = g_coef + ((size_t)bh*NC_ + ch)*160;
    for (int idx = lane; idx < 160; idx += 32) dst[idx] = CO[w][idx];
}

// ============================================================
// Kernel 2: chunked delta-rule scan (UT transform, T=8).
// CTA = 128 thr = 4 warps x 8 cols (C=2, L=8 — R14's proven
// swizzle/fill). 16-slot smem ring = 2 chunks of k/q.
// Per chunk:
//   P_i = k_i.S0, O_i = q_i.S0  (16 dots, ONE butterfly round)
//   d_i = be_i v_i - b_i P_i - sum_{j<i} M_ij d_j   (scalar)
//   o_i = G_i O_i + sum_{j<=i} N_ij d_j             (scalar)
//   S   = G_7 S + sum_j F_j k_j (x) d_j             (rank-8)
// ============================================================
typedef unsigned long long u64;

__device__ __forceinline__ u64 fma2(u64 a, u64 b, u64 c) {
    u64 d; asm("fma.rn.f32x2 %0, %1, %2, %3;" : "=l"(d) : "l"(a), "l"(b), "l"(c));
    return d;
}
__device__ __forceinline__ u64 mul2(u64 a, u64 b) {
    u64 d; asm("mul.rn.f32x2 %0, %1, %2;" : "=l"(d) : "l"(a), "l"(b));
    return d;
}
__device__ __forceinline__ u64 pack2(float x, float y) {
    u64 d; asm("mov.b64 %0, {%1, %2};" : "=l"(d)
               : "r"(__float_as_uint(x)), "r"(__float_as_uint(y)));
    return d;
}
__device__ __forceinline__ float hadd2(u64 a) {
    unsigned lo, hi;
    asm("mov.b64 {%0, %1}, %2;" : "=r"(lo), "=r"(hi) : "l"(a));
    return __uint_as_float(lo) + __uint_as_float(hi);
}

struct OctPre { float2 v[8]; };

__device__ __forceinline__ void load_oct(OctPre& p, const float* vb, int t0, int vq)
{
    #pragma unroll
    for (int i = 0; i < 8; ++i)
        p.v[i] = __ldg((const float2*)(vb + (size_t)(t0+i)*(H_*DK_)) + vq);
}

// process one chunk; pb = slot base (0 or 8), compile-time at call sites
__device__ __forceinline__ void do_chunk(const float4* sm, int pb,
                                         const float* cf, const OctPre& V,
                                         u64 st[16], const int ofs[4],
                                         int sub, int vq, float* orow0)
{
    const unsigned FM = 0xffffffffu;

    // ---- dots on S0 ----
    float P[8][2], O[8][2];
    #pragma unroll
    for (int i = 0; i < 8; ++i) {
        const float4* kreg = sm + ((pb + i)*2 + 0)*32;
        const float4* qreg = sm + ((pb + i)*2 + 1)*32;
        u64 k2[8];
        #pragma unroll
        for (int t = 0; t < 4; ++t) {
            ulonglong2 kk = *reinterpret_cast<const ulonglong2*>(kreg + ofs[t]);
            k2[2*t] = kk.x; k2[2*t+1] = kk.y;
        }
        u64 a0 = mul2(k2[0], st[0]);
        u64 a1 = mul2(k2[0], st[1]);
        #pragma unroll
        for (int m = 1; m < 8; ++m) {
            a0 = fma2(k2[m], st[m*2+0], a0);
            a1 = fma2(k2[m], st[m*2+1], a1);
        }
        P[i][0] = hadd2(a0); P[i][1] = hadd2(a1);

        u64 q2[8];
        #pragma unroll
        for (int t = 0; t < 4; ++t) {
            ulonglong2 qq = *reinterpret_cast<const ulonglong2*>(qreg + ofs[t]);
            q2[2*t] = qq.x; q2[2*t+1] = qq.y;
        }
        u64 b0 = mul2(q2[0], st[0]);
        u64 b1 = mul2(q2[0], st[1]);
        #pragma unroll
        for (int m = 1; m < 8; ++m) {
            b0 = fma2(q2[m], st[m*2+0], b0);
            b1 = fma2(q2[m], st[m*2+1], b1);
        }
        O[i][0] = hadd2(b0); O[i][1] = hadd2(b1);
    }

    // ---- single butterfly round over the 8 subs ----
    #pragma unroll
    for (int mm = 1; mm < 8; mm <<= 1) {
        #pragma unroll
        for (int i = 0; i < 8; ++i) {
            P[i][0] += __shfl_xor_sync(FM, P[i][0], mm);
            P[i][1] += __shfl_xor_sync(FM, P[i][1], mm);
            O[i][0] += __shfl_xor_sync(FM, O[i][0], mm);
            O[i][1] += __shfl_xor_sync(FM, O[i][1], mm);
        }
    }

    // ---- coefficient loads ----
    float4 c0 = __ldg((const float4*)(cf + 0));
    float4 c1 = __ldg((const float4*)(cf + 4));
    float4 c2 = __ldg((const float4*)(cf + 8));
    float4 c3 = __ldg((const float4*)(cf + 12));
    float4 c4 = __ldg((const float4*)(cf + 16));
    float4 c5 = __ldg((const float4*)(cf + 20));
    float4 c6 = __ldg((const float4*)(cf + 24));
    float4 c7 = __ldg((const float4*)(cf + 28));
    float bA[8]  = {c0.x,c0.y,c0.z,c0.w, c1.x,c1.y,c1.z,c1.w};
    float beA[8] = {c2.x,c2.y,c2.z,c2.w, c3.x,c3.y,c3.z,c3.w};
    float uA[8]  = {c4.x,c4.y,c4.z,c4.w, c5.x,c5.y,c5.z,c5.w};
    float FA[8]  = {c6.x,c6.y,c6.z,c6.w, c7.x,c7.y,c7.z,c7.w};

    // ---- serial scalar resolve + output ----
    float d[8][2];
    #pragma unroll
    for (int i = 0; i < 8; ++i) {
        float a0 = beA[i]*V.v[i].x - bA[i]*P[i][0];
        float a1 = beA[i]*V.v[i].y - bA[i]*P[i][1];
        if (i > 0) {
            float4 m0 = __ldg((const float4*)(cf + 32 + i*8));
            float4 m1 = __ldg((const float4*)(cf + 32 + i*8 + 4));
            float M[8] = {m0.x,m0.y,m0.z,m0.w, m1.x,m1.y,m1.z,m1.w};
            #pragma unroll
            for (int j = 0; j < i; ++j) {
                a0 -= M[j]*d[j][0];
                a1 -= M[j]*d[j][1];
            }
        }
        d[i][0] = a0; d[i][1] = a1;

        float4 n0 = __ldg((const float4*)(cf + 96 + i*8));
        float4 n1 = __ldg((const float4*)(cf + 96 + i*8 + 4));
        float N[8] = {n0.x,n0.y,n0.z,n0.w, n1.x,n1.y,n1.z,n1.w};
        float o0 = uA[i]*O[i][0];
        float o1 = uA[i]*O[i][1];
        #pragma unroll
        for (int j = 0; j <= i; ++j) {
            o0 += N[j]*d[j][0];
            o1 += N[j]*d[j][1];
        }
        if (sub == 0)
            ((float2*)(orow0 + (size_t)i*(H_*DV_)))[vq] = make_float2(o0, o1);
    }

    // ---- rank-8 state update ----
    u64 GT2 = pack2(uA[7], uA[7]);
    #pragma unroll
    for (int m = 0; m < 16; ++m) st[m] = mul2(GT2, st[m]);
    #pragma unroll
    for (int j = 0; j < 8; ++j) {
        const float4* kreg = sm + ((pb + j)*2 + 0)*32;
        u64 k2[8];
        #pragma unroll
        for (int t = 0; t < 4; ++t) {
            ulonglong2 kk = *reinterpret_cast<const ulonglong2*>(kreg + ofs[t]);
            k2[2*t] = kk.x; k2[2*t+1] = kk.y;
        }
        float e0 = FA[j]*d[j][0];
        float e1 = FA[j]*d[j][1];
        u64 e02 = pack2(e0, e0), e12 = pack2(e1, e1);
        #pragma unroll
        for (int m = 0; m < 8; ++m) {
            st[m*2+0] = fma2(k2[m], e02, st[m*2+0]);
            st[m*2+1] = fma2(k2[m], e12, st[m*2+1]);
        }
    }
}

__global__ void __launch_bounds__(128) scan_kernel(
    const float* __restrict__ q, const float* __restrict__ k,
    const float* __restrict__ v, float* __restrict__ out)
{
    // smem ring: 16 slots x {k,q} x 32 float4 (16 KB) = 2 chunks
    __shared__ float4 sm[16*2*32];

    int bid    = blockIdx.x;         // 256 CTAs
    int colcta = bid & 3;            // 32-col slice
    int bh     = bid >> 2;
    int b      = bh >> 4, h = bh & 15;
    int tid    = threadIdx.x;
    int w      = tid >> 5;           // warp 0..3
    int lane   = tid & 31;
    int cp     = lane >> 3;          // col-pair owner 0..3
    int sub    = lane & 7;           // row slice 0..7
    int col0   = colcta*32 + w*8 + cp*2;
    int vq     = col0 >> 1;          // float2 index

    size_t base = ((size_t)b * S_ * H_ + h) * DK_;
    const float* kb = k + base;
    const float* qb = q + base;
    const float* vb = v + base;
    float*       ob = out + base;
    const float* cfb = g_coef + (size_t)bh * NC_ * 160;

    // consumer LDS offsets (float4 units within a 32-float4 region)
    int ofs[4];
    #pragma unroll
    for (int t = 0; t < 4; ++t)
        ofs[t] = sub + 8*((t + sub) & 3);

    // fill params (R14-proven): warp w stages vector (w&1), slot parity (w>>1)
    int fvec  = w & 1;               // 0 = k, 1 = q
    int fsoff = w >> 1;              // 0 or 1
    int fidx  = (lane & 7) + 8*((((lane >> 3) + (lane & 7))) & 3);
    const float* fsrc = fvec ? qb : kb;

    // ---- pre-fill slots 0..15 = steps 0..15 (chunks 0,1) ----
    #pragma unroll
    for (int i2 = 0; i2 < 8; ++i2) {
        int fs = fsoff + 2*(i2 & 3) + 8*(i2 >> 2);   // slot = step
        float4 val = __ldg((const float4*)(fsrc + (size_t)fs*(H_*DK_)) + lane);
        sm[(fs*2 + fvec)*32 + fidx] = val;
    }
    __syncthreads();

    u64 st[16];
    #pragma unroll
    for (int j = 0; j < 16; ++j) st[j] = 0ull;

    OctPre Vc, Vn;
    load_oct(Vc, vb, 0, vq);

    for (int c = 0; c < NC_; c += 2) {
        // ===== chunk c (slots 0..7) =====
        load_oct(Vn, vb, (c+1)*CT_, vq);
        do_chunk(sm, 0, cfb + (size_t)c*160, Vc, st, ofs, sub, vq,
                 ob + (size_t)c*CT_*(H_*DV_));
        __syncthreads();
        {   // fill slots 0..7 <- chunk c+2
            int fc = (c + 2 < NC_) ? c + 2 : NC_ - 1;
            #pragma unroll
            for (int jj = 0; jj < 4; ++jj) {
                int srel = fsoff + 2*jj;
                float4 val = __ldg((const float4*)(fsrc +
                    (size_t)(fc*CT_ + srel)*(H_*DK_)) + lane);
                sm[(srel*2 + fvec)*32 + fidx] = val;
            }
        }
        Vc = Vn;

        // ===== chunk c+1 (slots 8..15) =====
        {
            int cn = (c + 2 < NC_) ? c + 2 : NC_ - 1;
            load_oct(Vn, vb, cn*CT_, vq);
        }
        do_chunk(sm, 8, cfb + (size_t)(c+1)*160, Vc, st, ofs, sub, vq,
                 ob + (size_t)(c+1)*CT_*(H_*DV_));
        __syncthreads();
        {   // fill slots 8..15 <- chunk c+3
            int fc = (c + 3 < NC_) ? c + 3 : NC_ - 1;
            #pragma unroll
            for (int jj = 0; jj < 4; ++jj) {
                int srel = fsoff + 2*jj;
                float4 val = __ldg((const float4*)(fsrc +
                    (size_t)(fc*CT_ + srel)*(H_*DK_)) + lane);
                sm[((8 + srel)*2 + fvec)*32 + fidx] = val;
            }
        }
        Vc = Vn;
    }
}

// ============================================================
extern "C" void kernel_launch(void* const* d_in, const int* in_sizes, int n_in,
                              void* d_out, int out_size)
{
    (void)in_sizes; (void)n_in; (void)out_size;
    const float* x   = (const float*)d_in[0];
    const float* q   = (const float*)d_in[1];
    const float* k   = (const float*)d_in[2];
    const float* v   = (const float*)d_in[3];
    const float* Wa  = (const float*)d_in[4];
    const float* Wb  = (const float*)d_in[5];
    const float* dtb = (const float*)d_in[6];
    const float* Al  = (const float*)d_in[7];
    float* out = (float*)d_out;

    gate_kernel<<<P_/GT_POS, 256>>>(x, Wa, Wb, dtb, Al);
    coef_kernel<<<(B_*H_*NC_)/4, 128>>>(q, k);
    scan_kernel<<<B_*H_*4, 128>>>(q, k, v, out);
}

// round 16
// speedup vs baseline: 1.1436x; 1.0895x over previous
#include <cuda_runtime.h>

#define B_   4
#define S_   2048
#define H_   16
#define HID_ 2048
#define DK_  128
#define DV_  128
#define P_   (B_*S_)   // 8192 positions

// scratch (allowed: __device__ globals)
__device__ float g_decay[P_*H_];
__device__ float g_beta [P_*H_];

// ============================================================
// Kernel 1: gating GEMM  raw = x @ [Wa;Wb]^T  + epilogue.
// Tile 64 pos x 32 outs, K-chunk 32, 256 thr, grid 128.
// 3-buffer smem ring + register-staged prefetch: LDG(c+2) ->
// compute(c) -> barrier -> STS(c+2). One barrier per chunk;
// ~400-cyc compute phase covers the LDG latency.
// ============================================================
#define GT_POS 64
#define GT_K   32

__global__ __launch_bounds__(256) void gate_kernel(
    const float* __restrict__ x,
    const float* __restrict__ Wa, const float* __restrict__ Wb,
    const float* __restrict__ dt_bias, const float* __restrict__ A_log)
{
    __shared__ float xs[3][GT_POS][GT_K+1];
    __shared__ float ws[3][32][GT_K+1];
    int t  = threadIdx.x;
    int p0 = blockIdx.x * GT_POS;
    int tx = t & 7;
    int ty = t >> 3;
    float acc[2][4] = {};

    const int NCHUNK = HID_ / GT_K;   // 64

    // per-thread fill coordinates
    int xr[8], xc[8], wf[4], wc[4];
    #pragma unroll
    for (int i = 0; i < 8; ++i) { int e = i*256 + t; xr[i] = e >> 5; xc[i] = e & 31; }
    #pragma unroll
    for (int i = 0; i < 4; ++i) { int e = i*256 + t; wf[i] = e >> 5; wc[i] = e & 31; }

    float rx[8], rw[4];

    // ---- prefill chunks 0,1 into buffers 0,1 ----
    #pragma unroll
    for (int c0 = 0; c0 < 2; ++c0) {
        int kc = c0 * GT_K;
        #pragma unroll
        for (int i = 0; i < 8; ++i)
            xs[c0][xr[i]][xc[i]] = x[(size_t)(p0 + xr[i])*HID_ + kc + xc[i]];
        #pragma unroll
        for (int i = 0; i < 4; ++i) {
            const float* wrow = (wf[i] < 16) ? (Wa + wf[i]*HID_) : (Wb + (wf[i]-16)*HID_);
            ws[c0][wf[i]][wc[i]] = wrow[kc + wc[i]];
        }
    }
    __syncthreads();

    for (int c = 0; c < NCHUNK; ++c) {
        // prefetch chunk c+2 into registers (covered by compute below)
        bool pf = (c + 2 < NCHUNK);
        if (pf) {
            int kc = (c + 2) * GT_K;
            #pragma unroll
            for (int i = 0; i < 8; ++i)
                rx[i] = x[(size_t)(p0 + xr[i])*HID_ + kc + xc[i]];
            #pragma unroll
            for (int i = 0; i < 4; ++i) {
                const float* wrow = (wf[i] < 16) ? (Wa + wf[i]*HID_) : (Wb + (wf[i]-16)*HID_);
                rw[i] = wrow[kc + wc[i]];
            }
        }

        // compute chunk c from buffer c%3
        int bi = c % 3;
        #pragma unroll
        for (int k = 0; k < GT_K; ++k) {
            float xv0 = xs[bi][2*ty  ][k];
            float xv1 = xs[bi][2*ty+1][k];
            #pragma unroll
            for (int j = 0; j < 4; ++j) {
                float wv = ws[bi][4*tx+j][k];
                acc[0][j] = fmaf(xv0, wv, acc[0][j]);
                acc[1][j] = fmaf(xv1, wv, acc[1][j]);
            }
        }
        __syncthreads();   // all warps done with chunk c (and c-1)

        if (pf) {
            int bo = (c + 2) % 3;
            #pragma unroll
            for (int i = 0; i < 8; ++i) xs[bo][xr[i]][xc[i]] = rx[i];
            #pragma unroll
            for (int i = 0; i < 4; ++i) ws[bo][wf[i]][wc[i]] = rw[i];
        }
        // visibility for compute(c+2): ordered by the barrier in iter c+1
    }

    #pragma unroll
    for (int i = 0; i < 2; ++i) {
        int p = p0 + 2*ty + i;
        #pragma unroll
        for (int j = 0; j < 4; ++j) {
            int f = 4*tx + j;
            float r = acc[i][j];
            if (f < 16) {
                float z  = r + __ldg(dt_bias + f);
                float sp = fmaxf(z, 0.0f) + log1pf(expf(-fabsf(z)));
                g_decay[p*H_ + f] = expf(-expf(__ldg(A_log + f)) * sp);
            } else {
                g_beta[p*H_ + (f-16)] = r;
            }
        }
    }
}

// ============================================================
// Kernel 2: delta-rule scan (R12 verbatim — measured 696 us).
// CTA = 256 thr = 8 warps; warp w owns 4 DV cols; grid = 64 bh x
// 4 colcta. Lane = (rg = lane>>2 owns rows 16rg..+15, co = lane&3
// owns col). State: 8 u64 (16 rows x 1 col). 8-slot static smem
// ring, 2 barriers per 8 steps.
// ============================================================
typedef unsigned long long u64;

__device__ __forceinline__ u64 fma2(u64 a, u64 b, u64 c) {
    u64 d; asm("fma.rn.f32x2 %0, %1, %2, %3;" : "=l"(d) : "l"(a), "l"(b), "l"(c));
    return d;
}
__device__ __forceinline__ u64 mul2(u64 a, u64 b) {
    u64 d; asm("mul.rn.f32x2 %0, %1, %2;" : "=l"(d) : "l"(a), "l"(b));
    return d;
}
__device__ __forceinline__ u64 pack2(float x, float y) {
    u64 d; asm("mov.b64 %0, {%1, %2};" : "=l"(d)
               : "r"(__float_as_uint(x)), "r"(__float_as_uint(y)));
    return d;
}
__device__ __forceinline__ float hadd2(u64 a) {
    unsigned lo, hi;
    asm("mov.b64 {%0, %1}, %2;" : "=r"(lo), "=r"(hi) : "l"(a));
    return __uint_as_float(lo) + __uint_as_float(hi);
}

struct QuadPre {                 // prefetched v/g/beta for 4 steps
    float v[4], g[4], b[4];
};

__device__ __forceinline__ void load_quad(QuadPre& p,
    const float* vb, const float* gb, const float* bb, int s, int col)
{
    #pragma unroll
    for (int i = 0; i < 4; ++i) {
        int si = s + i; if (si > S_ - 1) si = S_ - 1;
        p.v[i] = __ldg(vb + (size_t)si * (H_*DK_) + col);
        p.g[i] = __ldg(gb + (size_t)si * H_);
        p.b[i] = __ldg(bb + (size_t)si * H_);
    }
}

__device__ __forceinline__ void do_step(const float4* sm, int slot,
                                        u64 st[8], float v, float g, float be,
                                        float* outp, int rg, int col)
{
    const unsigned FM = 0xffffffffu;
    const float4* kslot = sm + (slot*2 + 0)*32;
    const float4* qslot = sm + (slot*2 + 1)*32;
    u64 k2[8], q2[8];
    #pragma unroll
    for (int i = 0; i < 4; ++i) {
        ulonglong2 kk = *reinterpret_cast<const ulonglong2*>(kslot + i*8 + rg);
        k2[2*i] = kk.x; k2[2*i+1] = kk.y;
        ulonglong2 qq = *reinterpret_cast<const ulonglong2*>(qslot + i*8 + rg);
        q2[2*i] = qq.x; q2[2*i+1] = qq.y;
    }

    // ---- p = k . S[:,col] ----
    u64 pa = mul2(k2[0], st[0]);
    u64 pb = mul2(k2[1], st[1]);
    #pragma unroll
    for (int j = 2; j < 8; j += 2) {
        pa = fma2(k2[j],   st[j],   pa);
        pb = fma2(k2[j+1], st[j+1], pb);
    }
    float p = hadd2(pa) + hadd2(pb);
    p += __shfl_xor_sync(FM, p, 4);
    p += __shfl_xor_sync(FM, p, 8);
    p += __shfl_xor_sync(FM, p, 16);

    // ---- delta ----
    float d = fmaf(-g, p, v) * be;

    // ---- state update: S = g*S + k (x) d ----
    u64 gp = pack2(g, g), dp = pack2(d, d);
    #pragma unroll
    for (int j = 0; j < 8; ++j)
        st[j] = fma2(k2[j], dp, mul2(gp, st[j]));

    // ---- o = q . S_new[:,col] (off recurrence critical path) ----
    u64 oa = mul2(q2[0], st[0]);
    u64 ob = mul2(q2[1], st[1]);
    #pragma unroll
    for (int j = 2; j < 8; j += 2) {
        oa = fma2(q2[j],   st[j],   oa);
        ob = fma2(q2[j+1], st[j+1], ob);
    }
    float o = hadd2(oa) + hadd2(ob);
    o += __shfl_xor_sync(FM, o, 4);
    o += __shfl_xor_sync(FM, o, 8);
    o += __shfl_xor_sync(FM, o, 16);

    if (rg == 0)
        outp[col] = o;
}

__global__ void __launch_bounds__(256, 2) scan_kernel(
    const float* __restrict__ q, const float* __restrict__ k,
    const float* __restrict__ v, float* __restrict__ out)
{
    // smem ring: 8 step slots x {k,q} x 32 float4 (8 KB)
    __shared__ float4 sm[8*2*32];

    int bid    = blockIdx.x;         // 256 CTAs
    int colcta = bid & 3;            // 32-col slice
    int bh     = bid >> 2;
    int b      = bh >> 4, h = bh & 15;
    int tid    = threadIdx.x;
    int w      = tid >> 5;           // warp 0..7
    int lane   = tid & 31;
    int rg     = lane >> 2;          // 0..7 row group (16 rows)
    int co     = lane & 3;           // col owner
    int col    = colcta*32 + w*4 + co;

    size_t base = ((size_t)b * S_ * H_ + h) * DK_;
    const float* kb = k + base;
    const float* qb = q + base;
    const float* vb = v + base;
    float*       ob = out + base;
    const float* gb = g_decay + (size_t)b * S_ * H_ + h;
    const float* bb = g_beta  + (size_t)b * S_ * H_ + h;

    // fill params: thread (vecsel = tid>>5, c = lane)
    int vecsel   = tid >> 5;         // (stepoff = vecsel>>1, kq = vecsel&1)
    int kq       = vecsel & 1;
    int fstep    = vecsel >> 1;      // 0..3
    int c        = lane;
    int perm     = ((c & 3) << 3) | (c >> 2);
    const float* fsrc = kq ? qb : kb;

    // ---- pre-fill slots 0..7 = steps 0..7 ----
    #pragma unroll
    for (int half = 0; half < 2; ++half) {
        int fs = half*4 + fstep;
        float4 val = __ldg((const float4*)(fsrc + (size_t)fs*(H_*DK_)) + c);
        sm[(fs*2 + kq)*32 + perm] = val;
    }
    __syncthreads();

    u64 st[8];
    #pragma unroll
    for (int j = 0; j < 8; ++j) st[j] = 0ull;

    QuadPre P0, P1;
    load_quad(P0, vb, gb, bb, 0, col);

    for (int s = 0; s < S_; s += 8) {
        load_quad(P1, vb, gb, bb, s + 4, col);

        // ---- consume slots 0..3 (steps s..s+3) ----
        do_step(sm, 0, st, P0.v[0], P0.g[0], P0.b[0], ob + (size_t)(s  )*(H_*DV_), rg, col);
        do_step(sm, 1, st, P0.v[1], P0.g[1], P0.b[1], ob + (size_t)(s+1)*(H_*DV_), rg, col);
        do_step(sm, 2, st, P0.v[2], P0.g[2], P0.b[2], ob + (size_t)(s+2)*(H_*DV_), rg, col);
        do_step(sm, 3, st, P0.v[3], P0.g[3], P0.b[3], ob + (size_t)(s+3)*(H_*DV_), rg, col);

        __syncthreads();   // slots 0..3 consumed by all warps

        // fill slots 0..3 <- steps s+8..s+11
        {
            int fs = s + 8 + fstep;
            if (fs > S_ - 1) fs = S_ - 1;
            float4 val = __ldg((const float4*)(fsrc + (size_t)fs*(H_*DK_)) + c);
            sm[(fstep*2 + kq)*32 + perm] = val;
        }
        load_quad(P0, vb, gb, bb, s + 8, col);   // for next iteration

        // ---- consume slots 4..7 (steps s+4..s+7) ----
        do_step(sm, 4, st, P1.v[0], P1.g[0], P1.b[0], ob + (size_t)(s+4)*(H_*DV_), rg, col);
        do_step(sm, 5, st, P1.v[1], P1.g[1], P1.b[1], ob + (size_t)(s+5)*(H_*DV_), rg, col);
        do_step(sm, 6, st, P1.v[2], P1.g[2], P1.b[2], ob + (size_t)(s+6)*(H_*DV_), rg, col);
        do_step(sm, 7, st, P1.v[3], P1.g[3], P1.b[3], ob + (size_t)(s+7)*(H_*DV_), rg, col);

        __syncthreads();   // slots 4..7 consumed

        // fill slots 4..7 <- steps s+12..s+15 (RAW ordered by next iter's
        // first barrier)
        {
            int fs = s + 12 + fstep;
            if (fs > S_ - 1) fs = S_ - 1;
            float4 val = __ldg((const float4*)(fsrc + (size_t)fs*(H_*DK_)) + c);
            sm[((4 + fstep)*2 + kq)*32 + perm] = val;
        }
    }
}

// ============================================================
extern "C" void kernel_launch(void* const* d_in, const int* in_sizes, int n_in,
                              void* d_out, int out_size)
{
    (void)in_sizes; (void)n_in; (void)out_size;
    const float* x   = (const float*)d_in[0];
    const float* q   = (const float*)d_in[1];
    const float* k   = (const float*)d_in[2];
    const float* v   = (const float*)d_in[3];
    const float* Wa  = (const float*)d_in[4];
    const float* Wb  = (const float*)d_in[5];
    const float* dtb = (const float*)d_in[6];
    const float* Al  = (const float*)d_in[7];
    float* out = (float*)d_out;

    gate_kernel<<<P_/GT_POS, 256>>>(x, Wa, Wb, dtb, Al);
    scan_kernel<<<B_*H_*4, 256>>>(q, k, v, out);
}

// round 17
// speedup vs baseline: 1.1492x; 1.0049x over previous
#include <cuda_runtime.h>

#define B_   4
#define S_   2048
#define H_   16
#define HID_ 2048
#define DK_  128
#define DV_  128
#define P_   (B_*S_)   // 8192 positions

// scratch (allowed: __device__ globals)
// interleaved per-(pos,h): [decay, beta]
__device__ float g_gb[P_*H_*2];

// ============================================================
// Kernel 1: gating GEMM  raw = x @ [Wa;Wb]^T  + epilogue.
// Tile 32 pos x 32 outs, K-chunk 32, 256 thr, grid 256 (all SMs).
// 3-buffer smem ring + register-staged prefetch: LDG(c+2) ->
// compute(c) -> barrier -> STS(c+2). One barrier per chunk.
// ============================================================
#define GT_POS 32
#define GT_K   32

__global__ __launch_bounds__(256) void gate_kernel(
    const float* __restrict__ x,
    const float* __restrict__ Wa, const float* __restrict__ Wb,
    const float* __restrict__ dt_bias, const float* __restrict__ A_log)
{
    __shared__ float xs[3][GT_POS][GT_K+1];
    __shared__ float ws[3][32][GT_K+1];
    int t  = threadIdx.x;
    int p0 = blockIdx.x * GT_POS;
    int tx = t & 7;    // f = 4*tx + j
    int ty = t >> 3;   // pos = p0 + ty
    float acc[4] = {};

    const int NCHUNK = HID_ / GT_K;   // 64

    // per-thread fill coordinates (4 elems each for xs and ws)
    int xr[4], xc[4];
    #pragma unroll
    for (int i = 0; i < 4; ++i) { int e = i*256 + t; xr[i] = e >> 5; xc[i] = e & 31; }

    float rx[4], rw[4];

    // ---- prefill chunks 0,1 into buffers 0,1 ----
    #pragma unroll
    for (int c0 = 0; c0 < 2; ++c0) {
        int kc = c0 * GT_K;
        #pragma unroll
        for (int i = 0; i < 4; ++i) {
            xs[c0][xr[i]][xc[i]] = x[(size_t)(p0 + xr[i])*HID_ + kc + xc[i]];
            const float* wrow = (xr[i] < 16) ? (Wa + xr[i]*HID_) : (Wb + (xr[i]-16)*HID_);
            ws[c0][xr[i]][xc[i]] = wrow[kc + xc[i]];
        }
    }
    __syncthreads();

    for (int c = 0; c < NCHUNK; ++c) {
        bool pf = (c + 2 < NCHUNK);
        if (pf) {
            int kc = (c + 2) * GT_K;
            #pragma unroll
            for (int i = 0; i < 4; ++i) {
                rx[i] = x[(size_t)(p0 + xr[i])*HID_ + kc + xc[i]];
                const float* wrow = (xr[i] < 16) ? (Wa + xr[i]*HID_) : (Wb + (xr[i]-16)*HID_);
                rw[i] = wrow[kc + xc[i]];
            }
        }

        int bi = c % 3;
        #pragma unroll
        for (int k = 0; k < GT_K; ++k) {
            float xv = xs[bi][ty][k];
            #pragma unroll
            for (int j = 0; j < 4; ++j)
                acc[j] = fmaf(xv, ws[bi][4*tx+j][k], acc[j]);
        }
        __syncthreads();

        if (pf) {
            int bo = (c + 2) % 3;
            #pragma unroll
            for (int i = 0; i < 4; ++i) {
                xs[bo][xr[i]][xc[i]] = rx[i];
                ws[bo][xr[i]][xc[i]] = rw[i];
            }
        }
    }

    int p = p0 + ty;
    #pragma unroll
    for (int j = 0; j < 4; ++j) {
        int f = 4*tx + j;
        float r = acc[j];
        if (f < 16) {
            float z  = r + __ldg(dt_bias + f);
            float sp = fmaxf(z, 0.0f) + log1pf(expf(-fabsf(z)));
            g_gb[((size_t)p*H_ + f)*2 + 0] = expf(-expf(__ldg(A_log + f)) * sp);
        } else {
            g_gb[((size_t)p*H_ + (f-16))*2 + 1] = r;
        }
    }
}

// ============================================================
// Kernel 2: delta-rule scan (R12 shape — measured 696-732 us).
// CTA = 256 thr = 8 warps; warp w owns 4 DV cols; grid = 64 bh x
// 4 colcta. Lane = (rg = lane>>2 owns rows 16rg..+15, co = lane&3
// owns col). State: 8 u64 (16 rows x 1 col). 8-slot static smem
// ring, 2 barriers per 8 steps.
// Micro-opts this round: fused [g,beta] LDG.64; q-slice LDS
// deferred until after the state update (cuts live registers
// through the dot/update phase).
// ============================================================
typedef unsigned long long u64;

__device__ __forceinline__ u64 fma2(u64 a, u64 b, u64 c) {
    u64 d; asm("fma.rn.f32x2 %0, %1, %2, %3;" : "=l"(d) : "l"(a), "l"(b), "l"(c));
    return d;
}
__device__ __forceinline__ u64 mul2(u64 a, u64 b) {
    u64 d; asm("mul.rn.f32x2 %0, %1, %2;" : "=l"(d) : "l"(a), "l"(b));
    return d;
}
__device__ __forceinline__ u64 pack2(float x, float y) {
    u64 d; asm("mov.b64 %0, {%1, %2};" : "=l"(d)
               : "r"(__float_as_uint(x)), "r"(__float_as_uint(y)));
    return d;
}
__device__ __forceinline__ float hadd2(u64 a) {
    unsigned lo, hi;
    asm("mov.b64 {%0, %1}, %2;" : "=r"(lo), "=r"(hi) : "l"(a));
    return __uint_as_float(lo) + __uint_as_float(hi);
}

struct QuadPre {                 // prefetched v / [g,b] for 4 steps
    float v[4];
    float2 gb[4];
};

__device__ __forceinline__ void load_quad(QuadPre& p,
    const float* vb, const float2* gb2, int s, int col)
{
    #pragma unroll
    for (int i = 0; i < 4; ++i) {
        int si = s + i; if (si > S_ - 1) si = S_ - 1;
        p.v[i]  = __ldg(vb + (size_t)si * (H_*DK_) + col);
        p.gb[i] = __ldg(gb2 + (size_t)si * H_);
    }
}

__device__ __forceinline__ void do_step(const float4* sm, int slot,
                                        u64 st[8], float v, float2 gbv,
                                        float* outp, int rg, int col)
{
    const unsigned FM = 0xffffffffu;
    const float4* kslot = sm + (slot*2 + 0)*32;
    const float4* qslot = sm + (slot*2 + 1)*32;
    u64 k2[8];
    #pragma unroll
    for (int i = 0; i < 4; ++i) {
        ulonglong2 kk = *reinterpret_cast<const ulonglong2*>(kslot + i*8 + rg);
        k2[2*i] = kk.x; k2[2*i+1] = kk.y;
    }

    // ---- p = k . S[:,col] ----
    u64 pa = mul2(k2[0], st[0]);
    u64 pb = mul2(k2[1], st[1]);
    #pragma unroll
    for (int j = 2; j < 8; j += 2) {
        pa = fma2(k2[j],   st[j],   pa);
        pb = fma2(k2[j+1], st[j+1], pb);
    }
    float p = hadd2(pa) + hadd2(pb);
    p += __shfl_xor_sync(FM, p, 4);
    p += __shfl_xor_sync(FM, p, 8);
    p += __shfl_xor_sync(FM, p, 16);

    // ---- delta ----
    float g = gbv.x;
    float d = fmaf(-g, p, v) * gbv.y;

    // ---- state update: S = g*S + k (x) d ----
    u64 gp = pack2(g, g), dp = pack2(d, d);
    #pragma unroll
    for (int j = 0; j < 8; ++j)
        st[j] = fma2(k2[j], dp, mul2(gp, st[j]));

    // ---- o = q . S_new[:,col] (q loaded only now; off recurrence path) ----
    u64 q2[8];
    #pragma unroll
    for (int i = 0; i < 4; ++i) {
        ulonglong2 qq = *reinterpret_cast<const ulonglong2*>(qslot + i*8 + rg);
        q2[2*i] = qq.x; q2[2*i+1] = qq.y;
    }
    u64 oa = mul2(q2[0], st[0]);
    u64 ob = mul2(q2[1], st[1]);
    #pragma unroll
    for (int j = 2; j < 8; j += 2) {
        oa = fma2(q2[j],   st[j],   oa);
        ob = fma2(q2[j+1], st[j+1], ob);
    }
    float o = hadd2(oa) + hadd2(ob);
    o += __shfl_xor_sync(FM, o, 4);
    o += __shfl_xor_sync(FM, o, 8);
    o += __shfl_xor_sync(FM, o, 16);

    if (rg == 0)
        outp[col] = o;
}

__global__ void __launch_bounds__(256, 2) scan_kernel(
    const float* __restrict__ q, const float* __restrict__ k,
    const float* __restrict__ v, float* __restrict__ out)
{
    // smem ring: 8 step slots x {k,q} x 32 float4 (8 KB)
    __shared__ float4 sm[8*2*32];

    int bid    = blockIdx.x;         // 256 CTAs
    int colcta = bid & 3;            // 32-col slice
    int bh     = bid >> 2;
    int b      = bh >> 4, h = bh & 15;
    int tid    = threadIdx.x;
    int w      = tid >> 5;           // warp 0..7
    int lane   = tid & 31;
    int rg     = lane >> 2;          // 0..7 row group (16 rows)
    int co     = lane & 3;           // col owner
    int col    = colcta*32 + w*4 + co;

    size_t base = ((size_t)b * S_ * H_ + h) * DK_;
    const float* kb = k + base;
    const float* qb = q + base;
    const float* vb = v + base;
    float*       ob = out + base;
    const float2* gb2 = (const float2*)g_gb + (size_t)b * S_ * H_ + h;

    // fill params: thread (vecsel = tid>>5, c = lane)
    int vecsel   = tid >> 5;
    int kq       = vecsel & 1;
    int fstep    = vecsel >> 1;      // 0..3
    int c        = lane;
    int perm     = ((c & 3) << 3) | (c >> 2);
    const float* fsrc = kq ? qb : kb;

    // ---- pre-fill slots 0..7 = steps 0..7 ----
    #pragma unroll
    for (int half = 0; half < 2; ++half) {
        int fs = half*4 + fstep;
        float4 val = __ldg((const float4*)(fsrc + (size_t)fs*(H_*DK_)) + c);
        sm[(fs*2 + kq)*32 + perm] = val;
    }
    __syncthreads();

    u64 st[8];
    #pragma unroll
    for (int j = 0; j < 8; ++j) st[j] = 0ull;

    QuadPre P0, P1;
    load_quad(P0, vb, gb2, 0, col);

    for (int s = 0; s < S_; s += 8) {
        load_quad(P1, vb, gb2, s + 4, col);

        // ---- consume slots 0..3 (steps s..s+3) ----
        do_step(sm, 0, st, P0.v[0], P0.gb[0], ob + (size_t)(s  )*(H_*DV_), rg, col);
        do_step(sm, 1, st, P0.v[1], P0.gb[1], ob + (size_t)(s+1)*(H_*DV_), rg, col);
        do_step(sm, 2, st, P0.v[2], P0.gb[2], ob + (size_t)(s+2)*(H_*DV_), rg, col);
        do_step(sm, 3, st, P0.v[3], P0.gb[3], ob + (size_t)(s+3)*(H_*DV_), rg, col);

        __syncthreads();   // slots 0..3 consumed by all warps

        // fill slots 0..3 <- steps s+8..s+11
        {
            int fs = s + 8 + fstep;
            if (fs > S_ - 1) fs = S_ - 1;
            float4 val = __ldg((const float4*)(fsrc + (size_t)fs*(H_*DK_)) + c);
            sm[(fstep*2 + kq)*32 + perm] = val;
        }
        load_quad(P0, vb, gb2, s + 8, col);   // for next iteration

        // ---- consume slots 4..7 (steps s+4..s+7) ----
        do_step(sm, 4, st, P1.v[0], P1.gb[0], ob + (size_t)(s+4)*(H_*DV_), rg, col);
        do_step(sm, 5, st, P1.v[1], P1.gb[1], ob + (size_t)(s+5)*(H_*DV_), rg, col);
        do_step(sm, 6, st, P1.v[2], P1.gb[2], ob + (size_t)(s+6)*(H_*DV_), rg, col);
        do_step(sm, 7, st, P1.v[3], P1.gb[3], ob + (size_t)(s+7)*(H_*DV_), rg, col);

        __syncthreads();   // slots 4..7 consumed

        // fill slots 4..7 <- steps s+12..s+15 (RAW ordered by next iter's
        // first barrier)
        {
            int fs = s + 12 + fstep;
            if (fs > S_ - 1) fs = S_ - 1;
            float4 val = __ldg((const float4*)(fsrc + (size_t)fs*(H_*DK_)) + c);
            sm[((4 + fstep)*2 + kq)*32 + perm] = val;
        }
    }
}

// ============================================================
extern "C" void kernel_launch(void* const* d_in, const int* in_sizes, int n_in,
                              void* d_out, int out_size)
{
    (void)in_sizes; (void)n_in; (void)out_size;
    const float* x   = (const float*)d_in[0];
    const float* q   = (const float*)d_in[1];
    const float* k   = (const float*)d_in[2];
    const float* v   = (const float*)d_in[3];
    const float* Wa  = (const float*)d_in[4];
    const float* Wb  = (const float*)d_in[5];
    const float* dtb = (const float*)d_in[6];
    const float* Al  = (const float*)d_in[7];
    float* out = (float*)d_out;

    gate_kernel<<<P_/GT_POS, 256>>>(x, Wa, Wb, dtb, Al);
    scan_kernel<<<B_*H_*4, 256>>>(q, k, v, out);
}